// round 3
// baseline (speedup 1.0000x reference)
#include <cuda_runtime.h>

// Problem constants (fixed by the dataset)
#define B_ 8
#define T_ 2048
#define D_ 1024
#define M_ (B_ * T_)          // 16384 rows
#define EPS_WKV 1e-9f
#define EPS_GN  1e-5f

// -------------------- device scratch (no allocations allowed) --------------------
__device__ float g_XR[(size_t)M_ * D_];   // mixed xr  ; later reused as pre-GN scan output
__device__ float g_XK[(size_t)M_ * D_];   // mixed xk
__device__ float g_XV[(size_t)M_ * D_];   // mixed xv
__device__ float g_R [(size_t)M_ * D_];   // sigmoid(xr @ Wr^T)
__device__ float g_EK[(size_t)M_ * D_];   // exp(xk @ Wk^T)
__device__ float g_V [(size_t)M_ * D_];   // xv @ Wv^T
__device__ float g_part[512];             // 256 warps x (sum, sumsq)
__device__ float g_stats[16];             // per-batch (mu, rstd)

// -------------------- f32x2 packed-FMA helpers (sm_100+) --------------------
__device__ __forceinline__ unsigned long long splat2(float a) {
    unsigned long long r;
    unsigned int u = __float_as_uint(a);
    asm("mov.b64 %0, {%1, %1};" : "=l"(r) : "r"(u));
    return r;
}
__device__ __forceinline__ void fma2(unsigned long long& c, unsigned long long a, unsigned long long b) {
    asm("fma.rn.f32x2 %0, %1, %2, %0;" : "+l"(c) : "l"(a), "l"(b));
}
__device__ __forceinline__ void unpack2(unsigned long long v, float& lo, float& hi) {
    asm("mov.b64 {%0, %1}, %2;" : "=f"(lo), "=f"(hi) : "l"(v));
}

// -------------------- 1) token-shift + time-mix --------------------
// xr = x*mr + x_prev*(1-mr), same for k, v.  x_prev[t=0] = state[:,0,:,2].
__global__ void mix_kernel(const float* __restrict__ x, const float* __restrict__ state,
                           const float* __restrict__ mr, const float* __restrict__ mk,
                           const float* __restrict__ mv)
{
    int i4 = blockIdx.x * blockDim.x + threadIdx.x;     // one float4 per thread
    int elem = i4 * 4;
    int d = elem & (D_ - 1);
    int t = (elem >> 10) & (T_ - 1);

    float4 xc = *(const float4*)(x + elem);
    float4 xp;
    if (t == 0) {
        int b = elem >> 21;                              // / (T_*D_)
        int s0 = ((b << 10) + d) * 3 + 2;                // state[(b*K + d)*3 + 2]
        xp.x = state[s0 + 0];
        xp.y = state[s0 + 3];
        xp.z = state[s0 + 6];
        xp.w = state[s0 + 9];
    } else {
        xp = *(const float4*)(x + elem - D_);
    }
    float4 r4 = *(const float4*)(mr + d);
    float4 k4 = *(const float4*)(mk + d);
    float4 v4 = *(const float4*)(mv + d);

    float4 o;
    o.x = xc.x * r4.x + xp.x * (1.f - r4.x);
    o.y = xc.y * r4.y + xp.y * (1.f - r4.y);
    o.z = xc.z * r4.z + xp.z * (1.f - r4.z);
    o.w = xc.w * r4.w + xp.w * (1.f - r4.w);
    *(float4*)(g_XR + elem) = o;

    o.x = xc.x * k4.x + xp.x * (1.f - k4.x);
    o.y = xc.y * k4.y + xp.y * (1.f - k4.y);
    o.z = xc.z * k4.z + xp.z * (1.f - k4.z);
    o.w = xc.w * k4.w + xp.w * (1.f - k4.w);
    *(float4*)(g_XK + elem) = o;

    o.x = xc.x * v4.x + xp.x * (1.f - v4.x);
    o.y = xc.y * v4.y + xp.y * (1.f - v4.y);
    o.z = xc.z * v4.z + xp.z * (1.f - v4.z);
    o.w = xc.w * v4.w + xp.w * (1.f - v4.w);
    *(float4*)(g_XV + elem) = o;
}

// -------------------- 2) SGEMM: C = A @ W^T, fused epilogues --------------------
// MODE 0: A=g_XR, C=g_R,  epi = sigmoid
// MODE 1: A=g_XK, C=g_EK, epi = exp
// MODE 2: A=g_XV, C=g_V,  epi = none
// MODE 3: A=g_XR (pre-GN scan output), normalize A on load, C=out
constexpr int BMt = 128, BNt = 128, BKt = 16, BPAD = 132;

template <int MODE>
__global__ void __launch_bounds__(256, 2)
gemm_kernel(const float* __restrict__ W, float* __restrict__ Cout,
            const float* __restrict__ gamma, const float* __restrict__ beta)
{
    __shared__ float As[BKt][BPAD];
    __shared__ float Bs[BKt][BPAD];

    const int tid = threadIdx.x;
    const int tx = tid & 15, ty = tid >> 4;
    const int m0 = blockIdx.y * BMt;
    const int n0 = blockIdx.x * BNt;

    const float* A = (MODE == 1) ? g_XK : (MODE == 2) ? g_XV : g_XR;
    float* C = (MODE == 0) ? g_R : (MODE == 1) ? g_EK : (MODE == 2) ? g_V : Cout;

    float mu = 0.f, rstd = 1.f;
    if (MODE == 3) {                       // 128 rows never cross a batch (2048 % 128 == 0)
        int b = m0 / T_;
        mu = g_stats[2 * b];
        rstd = g_stats[2 * b + 1];
    }

    unsigned long long acc[8][4];
#pragma unroll
    for (int i = 0; i < 8; i++)
#pragma unroll
        for (int j = 0; j < 4; j++) acc[i][j] = 0ull;

    for (int kt = 0; kt < D_; kt += BKt) {
        __syncthreads();
#pragma unroll
        for (int it = 0; it < 2; it++) {
            int f = tid + it * 256;        // 512 float4 per tile
            int r = f >> 2;                // 0..127
            int c4 = (f & 3) << 2;         // 0,4,8,12
            float4 av = *(const float4*)(A + (m0 + r) * D_ + kt + c4);
            if (MODE == 3) {
                av.x = (av.x - mu) * rstd * gamma[kt + c4 + 0] + beta[kt + c4 + 0];
                av.y = (av.y - mu) * rstd * gamma[kt + c4 + 1] + beta[kt + c4 + 1];
                av.z = (av.z - mu) * rstd * gamma[kt + c4 + 2] + beta[kt + c4 + 2];
                av.w = (av.w - mu) * rstd * gamma[kt + c4 + 3] + beta[kt + c4 + 3];
            }
            As[c4 + 0][r] = av.x; As[c4 + 1][r] = av.y;
            As[c4 + 2][r] = av.z; As[c4 + 3][r] = av.w;

            float4 bv = *(const float4*)(W + (n0 + r) * D_ + kt + c4);
            Bs[c4 + 0][r] = bv.x; Bs[c4 + 1][r] = bv.y;
            Bs[c4 + 2][r] = bv.z; Bs[c4 + 3][r] = bv.w;
        }
        __syncthreads();

#pragma unroll
        for (int k = 0; k < BKt; k++) {
            float4 a0 = *(const float4*)&As[k][ty * 8];
            float4 a1 = *(const float4*)&As[k][ty * 8 + 4];
            const unsigned long long* bp = (const unsigned long long*)&Bs[k][tx * 8];
            unsigned long long bb0 = bp[0], bb1 = bp[1], bb2 = bp[2], bb3 = bp[3];
            float aa[8] = {a0.x, a0.y, a0.z, a0.w, a1.x, a1.y, a1.z, a1.w};
#pragma unroll
            for (int i = 0; i < 8; i++) {
                unsigned long long a2 = splat2(aa[i]);
                fma2(acc[i][0], a2, bb0);
                fma2(acc[i][1], a2, bb1);
                fma2(acc[i][2], a2, bb2);
                fma2(acc[i][3], a2, bb3);
            }
        }
    }

    // epilogue
#pragma unroll
    for (int i = 0; i < 8; i++) {
        int m = m0 + ty * 8 + i;
        float* crow = C + m * D_ + n0 + tx * 8;
#pragma unroll
        for (int j = 0; j < 4; j++) {
            float lo, hi;
            unpack2(acc[i][j], lo, hi);
            if (MODE == 0) {
                lo = 1.f / (1.f + __expf(-lo));
                hi = 1.f / (1.f + __expf(-hi));
            } else if (MODE == 1) {
                lo = __expf(lo);
                hi = __expf(hi);
            }
            float2 st; st.x = lo; st.y = hi;
            *(float2*)(crow + 2 * j) = st;
        }
    }
}

// -------------------- 3) sequential WKV scan + GN partial stats --------------------
// One thread per (batch, channel): 8192 threads. Writes r*wkv into g_XR (reuse),
// accumulates per-warp (sum, sumsq) deterministically into g_part.
__global__ void scan_kernel(const float* __restrict__ state,
                            const float* __restrict__ decay,
                            const float* __restrict__ first)
{
    int g = blockIdx.x * blockDim.x + threadIdx.x;     // 0..8191
    int b = g >> 10, c = g & 1023;

    float w  = __expf(-__expf(decay[c]));
    float eu = __expf(first[c]);
    float num = state[g * 3 + 0];
    float den = state[g * 3 + 1];

    const float* pR  = g_R  + b * T_ * D_ + c;
    const float* pEK = g_EK + b * T_ * D_ + c;
    const float* pV  = g_V  + b * T_ * D_ + c;
    float*       pO  = g_XR + b * T_ * D_ + c;

    float sum = 0.f, sq = 0.f;
#pragma unroll 4
    for (int t = 0; t < T_; t++) {
        float ek = pEK[t * D_];
        float v  = pV [t * D_];
        float r  = pR [t * D_];
        float ee = eu * ek;
        float wkv = __fdividef(num + ee * v, den + ee + EPS_WKV);
        float o = r * wkv;
        pO[t * D_] = o;
        sum += o;
        sq  += o * o;
        num = num * w + ek * v;
        den = den * w + ek;
    }
    // warp reduction (all lanes in a warp share the same batch: 32 channels each)
#pragma unroll
    for (int off = 16; off; off >>= 1) {
        sum += __shfl_down_sync(0xffffffffu, sum, off);
        sq  += __shfl_down_sync(0xffffffffu, sq,  off);
    }
    if ((threadIdx.x & 31) == 0) {
        int wg = g >> 5;                                // 0..255
        g_part[wg * 2 + 0] = sum;
        g_part[wg * 2 + 1] = sq;
    }
}

// -------------------- 4) finalize GroupNorm stats (deterministic) --------------------
__global__ void stats_kernel()
{
    int b = blockIdx.x;          // 8 blocks
    int lane = threadIdx.x;      // 32 threads: 32 warps per batch
    float s = g_part[(b * 32 + lane) * 2 + 0];
    float q = g_part[(b * 32 + lane) * 2 + 1];
#pragma unroll
    for (int off = 16; off; off >>= 1) {
        s += __shfl_down_sync(0xffffffffu, s, off);
        q += __shfl_down_sync(0xffffffffu, q, off);
    }
    if (lane == 0) {
        const float N = (float)(T_ * D_);
        float mu = s / N;
        float var = q / N - mu * mu;
        g_stats[2 * b + 0] = mu;
        g_stats[2 * b + 1] = rsqrtf(var + EPS_GN);
    }
}

// -------------------- launch --------------------
extern "C" void kernel_launch(void* const* d_in, const int* in_sizes, int n_in,
                              void* d_out, int out_size)
{
    (void)in_sizes; (void)n_in; (void)out_size;
    const float* x     = (const float*)d_in[0];
    const float* state = (const float*)d_in[1];
    const float* Wr    = (const float*)d_in[2];
    const float* Wk    = (const float*)d_in[3];
    const float* Wv    = (const float*)d_in[4];
    const float* Wo    = (const float*)d_in[5];
    const float* mr    = (const float*)d_in[6];
    const float* mk    = (const float*)d_in[7];
    const float* mv    = (const float*)d_in[8];
    const float* decay = (const float*)d_in[9];
    const float* first = (const float*)d_in[10];
    const float* gam   = (const float*)d_in[11];
    const float* bet   = (const float*)d_in[12];
    float* out = (float*)d_out;

    mix_kernel<<<(M_ * D_ / 4) / 256, 256>>>(x, state, mr, mk, mv);

    dim3 gg(D_ / BNt, M_ / BMt);             // (8, 128)
    gemm_kernel<0><<<gg, 256>>>(Wr, nullptr, nullptr, nullptr);
    gemm_kernel<1><<<gg, 256>>>(Wk, nullptr, nullptr, nullptr);
    gemm_kernel<2><<<gg, 256>>>(Wv, nullptr, nullptr, nullptr);

    scan_kernel<<<32, 256>>>(state, decay, first);
    stats_kernel<<<8, 32>>>();

    gemm_kernel<3><<<gg, 256>>>(Wo, out, gam, bet);
}

// round 5
// speedup vs baseline: 3.1240x; 3.1240x over previous
#include <cuda_runtime.h>
#include <cstdint>

// Problem constants
#define B_ 8
#define T_ 2048
#define D_ 1024
#define M_ (B_ * T_)          // 16384
#define EPS_WKV 1e-9f
#define EPS_GN  1e-5f

// -------------------- device scratch (no allocations allowed) --------------------
__device__ float g_XR[(size_t)M_ * D_];   // xr mix; later reused as scan output
__device__ float g_XK[(size_t)M_ * D_];
__device__ float g_XV[(size_t)M_ * D_];
__device__ float g_R [(size_t)M_ * D_];
__device__ float g_EK[(size_t)M_ * D_];
__device__ float g_V [(size_t)M_ * D_];
__device__ float g_Wr[(size_t)D_ * D_];   // tf32-rounded weight copies
__device__ float g_Wk[(size_t)D_ * D_];
__device__ float g_Wv[(size_t)D_ * D_];
__device__ float g_Wg[(size_t)D_ * D_];   // tf32( gamma ⊙ W_o )
__device__ float g_c1[D_];                // sum_k gamma_k * Wo[n,k]
__device__ float g_c2[D_];                // sum_k beta_k  * Wo[n,k]
__device__ float g_part[512];
__device__ float g_stats[16];

// -------------------- helpers --------------------
__device__ __forceinline__ float tf32r(float f) {     // round-to-nearest tf32
    uint32_t u;
    asm("cvt.rna.tf32.f32 %0, %1;" : "=r"(u) : "f"(f));
    return __uint_as_float(u);
}
__device__ __forceinline__ void cp16(uint32_t dst, const void* src) {
    asm volatile("cp.async.cg.shared.global [%0], [%1], 16;" :: "r"(dst), "l"(src) : "memory");
}
__device__ __forceinline__ uint32_t smem_u32(const void* p) {
    uint32_t a;
    asm("{ .reg .u64 t; cvta.to.shared.u64 t, %1; cvt.u32.u64 %0, t; }" : "=r"(a) : "l"(p));
    return a;
}
__device__ __forceinline__ void mma_tf32(float* c, const uint32_t* a, const uint32_t* b) {
    asm volatile(
        "mma.sync.aligned.m16n8k8.row.col.f32.tf32.tf32.f32 "
        "{%0,%1,%2,%3}, {%4,%5,%6,%7}, {%8,%9}, {%0,%1,%2,%3};"
        : "+f"(c[0]), "+f"(c[1]), "+f"(c[2]), "+f"(c[3])
        : "r"(a[0]), "r"(a[1]), "r"(a[2]), "r"(a[3]), "r"(b[0]), "r"(b[1]));
}

// -------------------- 1) token-shift + time-mix (outputs tf32-rounded) --------------------
__global__ void mix_kernel(const float* __restrict__ x, const float* __restrict__ state,
                           const float* __restrict__ mr, const float* __restrict__ mk,
                           const float* __restrict__ mv)
{
    int i4 = blockIdx.x * blockDim.x + threadIdx.x;
    int elem = i4 * 4;
    int d = elem & (D_ - 1);
    int t = (elem >> 10) & (T_ - 1);

    float4 xc = *(const float4*)(x + elem);
    float4 xp;
    if (t == 0) {
        int b = elem >> 21;
        int s0 = ((b << 10) + d) * 3 + 2;
        xp.x = state[s0 + 0]; xp.y = state[s0 + 3];
        xp.z = state[s0 + 6]; xp.w = state[s0 + 9];
    } else {
        xp = *(const float4*)(x + elem - D_);
    }
    float4 r4 = *(const float4*)(mr + d);
    float4 k4 = *(const float4*)(mk + d);
    float4 v4 = *(const float4*)(mv + d);

    float4 o;
    o.x = tf32r(xc.x * r4.x + xp.x * (1.f - r4.x));
    o.y = tf32r(xc.y * r4.y + xp.y * (1.f - r4.y));
    o.z = tf32r(xc.z * r4.z + xp.z * (1.f - r4.z));
    o.w = tf32r(xc.w * r4.w + xp.w * (1.f - r4.w));
    *(float4*)(g_XR + elem) = o;

    o.x = tf32r(xc.x * k4.x + xp.x * (1.f - k4.x));
    o.y = tf32r(xc.y * k4.y + xp.y * (1.f - k4.y));
    o.z = tf32r(xc.z * k4.z + xp.z * (1.f - k4.z));
    o.w = tf32r(xc.w * k4.w + xp.w * (1.f - k4.w));
    *(float4*)(g_XK + elem) = o;

    o.x = tf32r(xc.x * v4.x + xp.x * (1.f - v4.x));
    o.y = tf32r(xc.y * v4.y + xp.y * (1.f - v4.y));
    o.z = tf32r(xc.z * v4.z + xp.z * (1.f - v4.z));
    o.w = tf32r(xc.w * v4.w + xp.w * (1.f - v4.w));
    *(float4*)(g_XV + elem) = o;
}

// -------------------- 1b) tf32-rounded weight copies --------------------
__global__ void round_w(const float* __restrict__ Wr, const float* __restrict__ Wk,
                        const float* __restrict__ Wv)
{
    int e = (blockIdx.x * blockDim.x + threadIdx.x) * 4;
    float4 a = *(const float4*)(Wr + e);
    a.x = tf32r(a.x); a.y = tf32r(a.y); a.z = tf32r(a.z); a.w = tf32r(a.w);
    *(float4*)(g_Wr + e) = a;
    a = *(const float4*)(Wk + e);
    a.x = tf32r(a.x); a.y = tf32r(a.y); a.z = tf32r(a.z); a.w = tf32r(a.w);
    *(float4*)(g_Wk + e) = a;
    a = *(const float4*)(Wv + e);
    a.x = tf32r(a.x); a.y = tf32r(a.y); a.z = tf32r(a.z); a.w = tf32r(a.w);
    *(float4*)(g_Wv + e) = a;
}

// -------------------- 1c) fold GroupNorm affine into W_o --------------------
__global__ void prep_wo(const float* __restrict__ Wo, const float* __restrict__ gam,
                        const float* __restrict__ bet)
{
    __shared__ float sh1[8], sh2[8];
    int n = blockIdx.x;
    float s1 = 0.f, s2 = 0.f;
    for (int k = threadIdx.x; k < D_; k += 256) {
        float w = Wo[n * D_ + k];
        float wg = tf32r(gam[k] * w);
        g_Wg[(size_t)n * D_ + k] = wg;
        s1 += wg;
        s2 += bet[k] * w;
    }
#pragma unroll
    for (int off = 16; off; off >>= 1) {
        s1 += __shfl_down_sync(0xffffffffu, s1, off);
        s2 += __shfl_down_sync(0xffffffffu, s2, off);
    }
    if ((threadIdx.x & 31) == 0) { sh1[threadIdx.x >> 5] = s1; sh2[threadIdx.x >> 5] = s2; }
    __syncthreads();
    if (threadIdx.x == 0) {
        float a = 0.f, b = 0.f;
        for (int i = 0; i < 8; i++) { a += sh1[i]; b += sh2[i]; }  // fixed order
        g_c1[n] = a; g_c2[n] = b;
    }
}

// -------------------- 2) tf32 mma.sync GEMM: C = A @ W^T + fused epilogue --------------------
// MODE 0: A=g_XR, W=g_Wr, C=g_R,  sigmoid
// MODE 1: A=g_XK, W=g_Wk, C=g_EK, exp
// MODE 2: A=g_XV, W=g_Wv, C=g_V,  none
// MODE 3: A=g_XR, W=g_Wg, C=out,  out = acc*rstd + (c2[n] - mu*rstd*c1[n])
constexpr int BKt = 32;
constexpr int NIT = D_ / BKt;                 // 32
constexpr int AST = 36;                       // padded row stride (floats): conflict-free
constexpr int TILE_FLOATS = 128 * AST;        // 4608 floats = 18432 B per matrix
constexpr int STAGE_BYTES = 2 * TILE_FLOATS * 4;    // 36864
constexpr int STAGES = 3;
constexpr int SMEM_SZ = STAGES * STAGE_BYTES;       // 110592

template <int MODE>
__global__ void __launch_bounds__(256, 2)
gemm_tc(float* __restrict__ Cout)
{
    extern __shared__ float smf[];
    uint32_t sb = smem_u32(smf);
    const int tid = threadIdx.x;
    const int wid = tid >> 5;
    const int lane = tid & 31;
    const int lr = lane >> 2;          // 0..7
    const int lc = lane & 3;           // 0..3
    const int wm = wid & 3;            // warp m index (4)
    const int wn = wid >> 2;           // warp n index (2)
    const int m0 = blockIdx.y * 128;
    const int n0 = blockIdx.x * 128;

    const float* A = (MODE == 1) ? g_XK : (MODE == 2) ? g_XV : g_XR;
    const float* W = (MODE == 0) ? g_Wr : (MODE == 1) ? g_Wk : (MODE == 2) ? g_Wv : g_Wg;
    float* C = (MODE == 0) ? g_R : (MODE == 1) ? g_EK : (MODE == 2) ? g_V : Cout;

    float c[2][8][4];
#pragma unroll
    for (int mi = 0; mi < 2; mi++)
#pragma unroll
        for (int ni = 0; ni < 8; ni++)
#pragma unroll
            for (int q = 0; q < 4; q++) c[mi][ni][q] = 0.f;

    // stage loader: A and W tiles, 128 rows x 32 floats each, padded stride 36
    auto load_stage = [&](int it, int s) {
        int kt = it * BKt;
        uint32_t ab = sb + s * STAGE_BYTES;
        uint32_t bb = ab + TILE_FLOATS * 4;
#pragma unroll
        for (int i = 0; i < 4; i++) {
            int g = tid + i * 256;            // 0..1023
            int row = g >> 3;
            int c4 = g & 7;
            cp16(ab + row * (AST * 4) + c4 * 16, A + (size_t)(m0 + row) * D_ + kt + c4 * 4);
            cp16(bb + row * (AST * 4) + c4 * 16, W + (size_t)(n0 + row) * D_ + kt + c4 * 4);
        }
        asm volatile("cp.async.commit_group;" ::: "memory");
    };

    load_stage(0, 0);
    load_stage(1, 1);
    asm volatile("cp.async.wait_group 1;" ::: "memory");
    __syncthreads();

    for (int kt = 0; kt < NIT; kt++) {
        int s = kt % STAGES;
        if (kt + 2 < NIT) load_stage(kt + 2, (kt + 2) % STAGES);

        const float* As = smf + (size_t)s * (2 * TILE_FLOATS);
        const float* Bs = As + TILE_FLOATS;
#pragma unroll
        for (int k0 = 0; k0 < BKt; k0 += 8) {
            uint32_t a[2][4], bf[8][2];
#pragma unroll
            for (int mi = 0; mi < 2; mi++) {
                const float* ap = As + (wm * 32 + mi * 16 + lr) * AST + k0 + lc;
                a[mi][0] = __float_as_uint(ap[0]);
                a[mi][1] = __float_as_uint(ap[8 * AST]);
                a[mi][2] = __float_as_uint(ap[4]);
                a[mi][3] = __float_as_uint(ap[8 * AST + 4]);
            }
#pragma unroll
            for (int ni = 0; ni < 8; ni++) {
                const float* bp = Bs + (wn * 64 + ni * 8 + lr) * AST + k0 + lc;
                bf[ni][0] = __float_as_uint(bp[0]);
                bf[ni][1] = __float_as_uint(bp[4]);
            }
#pragma unroll
            for (int mi = 0; mi < 2; mi++)
#pragma unroll
                for (int ni = 0; ni < 8; ni++)
                    mma_tf32(c[mi][ni], a[mi], bf[ni]);
        }

        if (kt < NIT - 1) {
            if (kt + 2 < NIT) asm volatile("cp.async.wait_group 1;" ::: "memory");
            else              asm volatile("cp.async.wait_group 0;" ::: "memory");
            __syncthreads();
        }
    }

    // epilogue
    float mu = 0.f, rstd = 1.f;
    if (MODE == 3) {
        int b = m0 / T_;
        mu = g_stats[2 * b]; rstd = g_stats[2 * b + 1];
    }
#pragma unroll
    for (int mi = 0; mi < 2; mi++) {
#pragma unroll
        for (int half = 0; half < 2; half++) {
            int m = m0 + wm * 32 + mi * 16 + lr + half * 8;
            float* crow = C + (size_t)m * D_ + n0 + wn * 64 + lc * 2;
#pragma unroll
            for (int ni = 0; ni < 8; ni++) {
                float v0 = c[mi][ni][half * 2 + 0];
                float v1 = c[mi][ni][half * 2 + 1];
                float2 o;
                if (MODE == 0) {
                    o.x = 1.f / (1.f + __expf(-v0));
                    o.y = 1.f / (1.f + __expf(-v1));
                } else if (MODE == 1) {
                    o.x = __expf(v0); o.y = __expf(v1);
                } else if (MODE == 2) {
                    o.x = v0; o.y = v1;
                } else {
                    int n = n0 + wn * 64 + ni * 8 + lc * 2;
                    o.x = v0 * rstd + (g_c2[n + 0] - mu * rstd * g_c1[n + 0]);
                    o.y = v1 * rstd + (g_c2[n + 1] - mu * rstd * g_c1[n + 1]);
                }
                *(float2*)(crow + ni * 8) = o;
            }
        }
    }
}

// -------------------- 3) sequential WKV scan + GN partials --------------------
__global__ void scan_kernel(const float* __restrict__ state,
                            const float* __restrict__ decay,
                            const float* __restrict__ first)
{
    int g = blockIdx.x * blockDim.x + threadIdx.x;     // 0..8191
    int b = g >> 10, c = g & 1023;

    float w  = __expf(-__expf(decay[c]));
    float eu = __expf(first[c]);
    float num = state[g * 3 + 0];
    float den = state[g * 3 + 1];

    const float* pR  = g_R  + (size_t)b * T_ * D_ + c;
    const float* pEK = g_EK + (size_t)b * T_ * D_ + c;
    const float* pV  = g_V  + (size_t)b * T_ * D_ + c;
    float*       pO  = g_XR + (size_t)b * T_ * D_ + c;   // reuse as scan output

    float sum = 0.f, sq = 0.f;
#pragma unroll 4
    for (int t = 0; t < T_; t++) {
        float ek = pEK[(size_t)t * D_];
        float v  = pV [(size_t)t * D_];
        float r  = pR [(size_t)t * D_];
        float ee = eu * ek;
        float wkv = __fdividef(num + ee * v, den + ee + EPS_WKV);
        float o = tf32r(r * wkv);                        // pre-round for GEMM-4 input
        pO[(size_t)t * D_] = o;
        sum += o;
        sq  += o * o;
        num = num * w + ek * v;
        den = den * w + ek;
    }
#pragma unroll
    for (int off = 16; off; off >>= 1) {
        sum += __shfl_down_sync(0xffffffffu, sum, off);
        sq  += __shfl_down_sync(0xffffffffu, sq,  off);
    }
    if ((threadIdx.x & 31) == 0) {
        int wg = g >> 5;
        g_part[wg * 2 + 0] = sum;
        g_part[wg * 2 + 1] = sq;
    }
}

__global__ void stats_kernel()
{
    int b = blockIdx.x;
    int lane = threadIdx.x;
    float s = g_part[(b * 32 + lane) * 2 + 0];
    float q = g_part[(b * 32 + lane) * 2 + 1];
#pragma unroll
    for (int off = 16; off; off >>= 1) {
        s += __shfl_down_sync(0xffffffffu, s, off);
        q += __shfl_down_sync(0xffffffffu, q, off);
    }
    if (lane == 0) {
        const float N = (float)(T_ * D_);
        float mu = s / N;
        float var = q / N - mu * mu;
        g_stats[2 * b + 0] = mu;
        g_stats[2 * b + 1] = rsqrtf(var + EPS_GN);
    }
}

// -------------------- launch --------------------
extern "C" void kernel_launch(void* const* d_in, const int* in_sizes, int n_in,
                              void* d_out, int out_size)
{
    (void)in_sizes; (void)n_in; (void)out_size;
    const float* x     = (const float*)d_in[0];
    const float* state = (const float*)d_in[1];
    const float* Wr    = (const float*)d_in[2];
    const float* Wk    = (const float*)d_in[3];
    const float* Wv    = (const float*)d_in[4];
    const float* Wo    = (const float*)d_in[5];
    const float* mr    = (const float*)d_in[6];
    const float* mk    = (const float*)d_in[7];
    const float* mv    = (const float*)d_in[8];
    const float* decay = (const float*)d_in[9];
    const float* first = (const float*)d_in[10];
    const float* gam   = (const float*)d_in[11];
    const float* bet   = (const float*)d_in[12];
    float* out = (float*)d_out;

    static bool attr_done = false;
    if (!attr_done) {
        cudaFuncSetAttribute(gemm_tc<0>, cudaFuncAttributeMaxDynamicSharedMemorySize, SMEM_SZ);
        cudaFuncSetAttribute(gemm_tc<1>, cudaFuncAttributeMaxDynamicSharedMemorySize, SMEM_SZ);
        cudaFuncSetAttribute(gemm_tc<2>, cudaFuncAttributeMaxDynamicSharedMemorySize, SMEM_SZ);
        cudaFuncSetAttribute(gemm_tc<3>, cudaFuncAttributeMaxDynamicSharedMemorySize, SMEM_SZ);
        attr_done = true;
    }

    round_w<<<(D_ * D_ / 4) / 256, 256>>>(Wr, Wk, Wv);
    prep_wo<<<D_, 256>>>(Wo, gam, bet);
    mix_kernel<<<(M_ * D_ / 4) / 256, 256>>>(x, state, mr, mk, mv);

    dim3 gg(D_ / 128, M_ / 128);             // (8, 128)
    gemm_tc<0><<<gg, 256, SMEM_SZ>>>(nullptr);
    gemm_tc<1><<<gg, 256, SMEM_SZ>>>(nullptr);
    gemm_tc<2><<<gg, 256, SMEM_SZ>>>(nullptr);

    scan_kernel<<<32, 256>>>(state, decay, first);
    stats_kernel<<<8, 32>>>();

    gemm_tc<3><<<gg, 256, SMEM_SZ>>>(out);
}

// round 8
// speedup vs baseline: 6.3539x; 2.0339x over previous
#include <cuda_runtime.h>
#include <cstdint>

// Problem constants
#define B_ 8
#define T_ 2048
#define D_ 1024
#define M_ (B_ * T_)          // 16384
#define EPS_WKV 1e-9f
#define EPS_GN  1e-5f
#define CH_ 16                 // scan chunks
#define L_ (T_ / CH_)          // 128 steps per chunk

// -------------------- device scratch (no allocations allowed) --------------------
__device__ float g_XR[(size_t)M_ * D_];   // xr mix; later reused as scan output
__device__ float g_XK[(size_t)M_ * D_];
__device__ float g_XV[(size_t)M_ * D_];
__device__ float g_R [(size_t)M_ * D_];
__device__ float g_EK[(size_t)M_ * D_];
__device__ float g_V [(size_t)M_ * D_];
__device__ float g_Wr[(size_t)D_ * D_];   // tf32-rounded weight copies
__device__ float g_Wk[(size_t)D_ * D_];
__device__ float g_Wv[(size_t)D_ * D_];
__device__ float g_Wg[(size_t)D_ * D_];   // tf32( gamma ⊙ W_o )
__device__ float g_c1[D_];                // sum_k gamma_k * Wo[n,k]
__device__ float g_c2[D_];                // sum_k beta_k  * Wo[n,k]
__device__ float g_locN[CH_ * B_ * 1024]; // chunk-local scan sums
__device__ float g_locD[CH_ * B_ * 1024];
__device__ float g_carN[CH_ * B_ * 1024]; // per-chunk carry-in
__device__ float g_carD[CH_ * B_ * 1024];
__device__ float g_part[8192];            // 4096 warps x (sum, sumsq)
__device__ float g_stats[16];             // per-batch (mu, rstd)

// -------------------- helpers --------------------
__device__ __forceinline__ float tf32r(float f) {     // round-to-nearest tf32
    uint32_t u;
    asm("cvt.rna.tf32.f32 %0, %1;" : "=r"(u) : "f"(f));
    return __uint_as_float(u);
}
__device__ __forceinline__ void cp16(uint32_t dst, const void* src) {
    asm volatile("cp.async.cg.shared.global [%0], [%1], 16;" :: "r"(dst), "l"(src) : "memory");
}
__device__ __forceinline__ uint32_t smem_u32(const void* p) {
    uint32_t a;
    asm("{ .reg .u64 t; cvta.to.shared.u64 t, %1; cvt.u32.u64 %0, t; }" : "=r"(a) : "l"(p));
    return a;
}
__device__ __forceinline__ void mma_tf32(float* c, const uint32_t* a, const uint32_t* b) {
    asm volatile(
        "mma.sync.aligned.m16n8k8.row.col.f32.tf32.tf32.f32 "
        "{%0,%1,%2,%3}, {%4,%5,%6,%7}, {%8,%9}, {%0,%1,%2,%3};"
        : "+f"(c[0]), "+f"(c[1]), "+f"(c[2]), "+f"(c[3])
        : "r"(a[0]), "r"(a[1]), "r"(a[2]), "r"(a[3]), "r"(b[0]), "r"(b[1]));
}

// -------------------- 1) token-shift + time-mix (outputs tf32-rounded) --------------------
__global__ void mix_kernel(const float* __restrict__ x, const float* __restrict__ state,
                           const float* __restrict__ mr, const float* __restrict__ mk,
                           const float* __restrict__ mv)
{
    int i4 = blockIdx.x * blockDim.x + threadIdx.x;
    int elem = i4 * 4;
    int d = elem & (D_ - 1);
    int t = (elem >> 10) & (T_ - 1);

    float4 xc = *(const float4*)(x + elem);
    float4 xp;
    if (t == 0) {
        int b = elem >> 21;
        int s0 = ((b << 10) + d) * 3 + 2;
        xp.x = state[s0 + 0]; xp.y = state[s0 + 3];
        xp.z = state[s0 + 6]; xp.w = state[s0 + 9];
    } else {
        xp = *(const float4*)(x + elem - D_);
    }
    float4 r4 = *(const float4*)(mr + d);
    float4 k4 = *(const float4*)(mk + d);
    float4 v4 = *(const float4*)(mv + d);

    float4 o;
    o.x = tf32r(xc.x * r4.x + xp.x * (1.f - r4.x));
    o.y = tf32r(xc.y * r4.y + xp.y * (1.f - r4.y));
    o.z = tf32r(xc.z * r4.z + xp.z * (1.f - r4.z));
    o.w = tf32r(xc.w * r4.w + xp.w * (1.f - r4.w));
    *(float4*)(g_XR + elem) = o;

    o.x = tf32r(xc.x * k4.x + xp.x * (1.f - k4.x));
    o.y = tf32r(xc.y * k4.y + xp.y * (1.f - k4.y));
    o.z = tf32r(xc.z * k4.z + xp.z * (1.f - k4.z));
    o.w = tf32r(xc.w * k4.w + xp.w * (1.f - k4.w));
    *(float4*)(g_XK + elem) = o;

    o.x = tf32r(xc.x * v4.x + xp.x * (1.f - v4.x));
    o.y = tf32r(xc.y * v4.y + xp.y * (1.f - v4.y));
    o.z = tf32r(xc.z * v4.z + xp.z * (1.f - v4.z));
    o.w = tf32r(xc.w * v4.w + xp.w * (1.f - v4.w));
    *(float4*)(g_XV + elem) = o;
}

// -------------------- 1b) tf32-rounded weight copies --------------------
__global__ void round_w(const float* __restrict__ Wr, const float* __restrict__ Wk,
                        const float* __restrict__ Wv)
{
    int e = (blockIdx.x * blockDim.x + threadIdx.x) * 4;
    float4 a = *(const float4*)(Wr + e);
    a.x = tf32r(a.x); a.y = tf32r(a.y); a.z = tf32r(a.z); a.w = tf32r(a.w);
    *(float4*)(g_Wr + e) = a;
    a = *(const float4*)(Wk + e);
    a.x = tf32r(a.x); a.y = tf32r(a.y); a.z = tf32r(a.z); a.w = tf32r(a.w);
    *(float4*)(g_Wk + e) = a;
    a = *(const float4*)(Wv + e);
    a.x = tf32r(a.x); a.y = tf32r(a.y); a.z = tf32r(a.z); a.w = tf32r(a.w);
    *(float4*)(g_Wv + e) = a;
}

// -------------------- 1c) fold GroupNorm affine into W_o --------------------
__global__ void prep_wo(const float* __restrict__ Wo, const float* __restrict__ gam,
                        const float* __restrict__ bet)
{
    __shared__ float sh1[8], sh2[8];
    int n = blockIdx.x;
    float s1 = 0.f, s2 = 0.f;
    for (int k = threadIdx.x; k < D_; k += 256) {
        float w = Wo[n * D_ + k];
        float wg = tf32r(gam[k] * w);
        g_Wg[(size_t)n * D_ + k] = wg;
        s1 += wg;
        s2 += bet[k] * w;
    }
#pragma unroll
    for (int off = 16; off; off >>= 1) {
        s1 += __shfl_down_sync(0xffffffffu, s1, off);
        s2 += __shfl_down_sync(0xffffffffu, s2, off);
    }
    if ((threadIdx.x & 31) == 0) { sh1[threadIdx.x >> 5] = s1; sh2[threadIdx.x >> 5] = s2; }
    __syncthreads();
    if (threadIdx.x == 0) {
        float a = 0.f, b = 0.f;
        for (int i = 0; i < 8; i++) { a += sh1[i]; b += sh2[i]; }  // fixed order
        g_c1[n] = a; g_c2[n] = b;
    }
}

// -------------------- 2) tf32 mma.sync GEMM (unchanged, known good) --------------------
constexpr int BKt = 32;
constexpr int NIT = D_ / BKt;                 // 32
constexpr int AST = 36;                       // padded row stride (floats)
constexpr int TILE_FLOATS = 128 * AST;
constexpr int STAGE_BYTES = 2 * TILE_FLOATS * 4;
constexpr int STAGES = 3;
constexpr int SMEM_SZ = STAGES * STAGE_BYTES; // 110592

template <int MODE>
__global__ void __launch_bounds__(256, 2)
gemm_tc(float* __restrict__ Cout)
{
    extern __shared__ float smf[];
    uint32_t sb = smem_u32(smf);
    const int tid = threadIdx.x;
    const int wid = tid >> 5;
    const int lane = tid & 31;
    const int lr = lane >> 2;
    const int lc = lane & 3;
    const int wm = wid & 3;
    const int wn = wid >> 2;
    const int m0 = blockIdx.y * 128;
    const int n0 = blockIdx.x * 128;

    const float* A = (MODE == 1) ? g_XK : (MODE == 2) ? g_XV : g_XR;
    const float* W = (MODE == 0) ? g_Wr : (MODE == 1) ? g_Wk : (MODE == 2) ? g_Wv : g_Wg;
    float* C = (MODE == 0) ? g_R : (MODE == 1) ? g_EK : (MODE == 2) ? g_V : Cout;

    float c[2][8][4];
#pragma unroll
    for (int mi = 0; mi < 2; mi++)
#pragma unroll
        for (int ni = 0; ni < 8; ni++)
#pragma unroll
            for (int q = 0; q < 4; q++) c[mi][ni][q] = 0.f;

    auto load_stage = [&](int it, int s) {
        int kt = it * BKt;
        uint32_t ab = sb + s * STAGE_BYTES;
        uint32_t bb = ab + TILE_FLOATS * 4;
#pragma unroll
        for (int i = 0; i < 4; i++) {
            int g = tid + i * 256;
            int row = g >> 3;
            int c4 = g & 7;
            cp16(ab + row * (AST * 4) + c4 * 16, A + (size_t)(m0 + row) * D_ + kt + c4 * 4);
            cp16(bb + row * (AST * 4) + c4 * 16, W + (size_t)(n0 + row) * D_ + kt + c4 * 4);
        }
        asm volatile("cp.async.commit_group;" ::: "memory");
    };

    load_stage(0, 0);
    load_stage(1, 1);
    asm volatile("cp.async.wait_group 1;" ::: "memory");
    __syncthreads();

    for (int kt = 0; kt < NIT; kt++) {
        int s = kt % STAGES;
        if (kt + 2 < NIT) load_stage(kt + 2, (kt + 2) % STAGES);

        const float* As = smf + (size_t)s * (2 * TILE_FLOATS);
        const float* Bs = As + TILE_FLOATS;
#pragma unroll
        for (int k0 = 0; k0 < BKt; k0 += 8) {
            uint32_t a[2][4], bf[8][2];
#pragma unroll
            for (int mi = 0; mi < 2; mi++) {
                const float* ap = As + (wm * 32 + mi * 16 + lr) * AST + k0 + lc;
                a[mi][0] = __float_as_uint(ap[0]);
                a[mi][1] = __float_as_uint(ap[8 * AST]);
                a[mi][2] = __float_as_uint(ap[4]);
                a[mi][3] = __float_as_uint(ap[8 * AST + 4]);
            }
#pragma unroll
            for (int ni = 0; ni < 8; ni++) {
                const float* bp = Bs + (wn * 64 + ni * 8 + lr) * AST + k0 + lc;
                bf[ni][0] = __float_as_uint(bp[0]);
                bf[ni][1] = __float_as_uint(bp[4]);
            }
#pragma unroll
            for (int mi = 0; mi < 2; mi++)
#pragma unroll
                for (int ni = 0; ni < 8; ni++)
                    mma_tf32(c[mi][ni], a[mi], bf[ni]);
        }

        if (kt < NIT - 1) {
            if (kt + 2 < NIT) asm volatile("cp.async.wait_group 1;" ::: "memory");
            else              asm volatile("cp.async.wait_group 0;" ::: "memory");
            __syncthreads();
        }
    }

    float mu = 0.f, rstd = 1.f;
    if (MODE == 3) {
        int b = m0 / T_;
        mu = g_stats[2 * b]; rstd = g_stats[2 * b + 1];
    }
#pragma unroll
    for (int mi = 0; mi < 2; mi++) {
#pragma unroll
        for (int half = 0; half < 2; half++) {
            int m = m0 + wm * 32 + mi * 16 + lr + half * 8;
            float* crow = C + (size_t)m * D_ + n0 + wn * 64 + lc * 2;
#pragma unroll
            for (int ni = 0; ni < 8; ni++) {
                float v0 = c[mi][ni][half * 2 + 0];
                float v1 = c[mi][ni][half * 2 + 1];
                float2 o;
                if (MODE == 0) {
                    o.x = 1.f / (1.f + __expf(-v0));
                    o.y = 1.f / (1.f + __expf(-v1));
                } else if (MODE == 1) {
                    o.x = __expf(v0); o.y = __expf(v1);
                } else if (MODE == 2) {
                    o.x = v0; o.y = v1;
                } else {
                    int n = n0 + wn * 64 + ni * 8 + lc * 2;
                    o.x = v0 * rstd + (g_c2[n + 0] - mu * rstd * g_c1[n + 0]);
                    o.y = v1 * rstd + (g_c2[n + 1] - mu * rstd * g_c1[n + 1]);
                }
                *(float2*)(crow + ni * 8) = o;
            }
        }
    }
}

// -------------------- 3) chunk-parallel WKV scan --------------------
// thread id g = (chunk*8 + b)*1024 + c  → 131072 threads, full chip
__global__ void scan_part1(const float* __restrict__ decay)
{
    int g = blockIdx.x * blockDim.x + threadIdx.x;
    int c = g & 1023;
    int cb = g >> 10;
    int b = cb & 7;
    int chunk = cb >> 3;

    float w = __expf(-__expf(decay[c]));
    const float* pEK = g_EK + ((size_t)(b * T_ + chunk * L_)) * D_ + c;
    const float* pV  = g_V  + ((size_t)(b * T_ + chunk * L_)) * D_ + c;

    float num = 0.f, den = 0.f;
#pragma unroll 4
    for (int t = 0; t < L_; t++) {
        float ek = pEK[(size_t)t * D_];
        float v  = pV [(size_t)t * D_];
        num = num * w + ek * v;
        den = den * w + ek;
    }
    g_locN[g] = num;
    g_locD[g] = den;
}

__global__ void scan_part2(const float* __restrict__ state, const float* __restrict__ decay)
{
    int g = blockIdx.x * blockDim.x + threadIdx.x;     // 0..8191
    int c = g & 1023;
    int b = g >> 10;
    float wL = __expf(-__expf(decay[c]) * (float)L_);  // w^L in exact closed form
    float cn = state[((b << 10) + c) * 3 + 0];
    float cd = state[((b << 10) + c) * 3 + 1];
#pragma unroll
    for (int chunk = 0; chunk < CH_; chunk++) {
        int idx = ((chunk << 3) + b) * 1024 + c;
        g_carN[idx] = cn;
        g_carD[idx] = cd;
        cn = cn * wL + g_locN[idx];
        cd = cd * wL + g_locD[idx];
    }
}

__global__ void scan_part3(const float* __restrict__ decay, const float* __restrict__ first)
{
    int g = blockIdx.x * blockDim.x + threadIdx.x;
    int c = g & 1023;
    int cb = g >> 10;
    int b = cb & 7;
    int chunk = cb >> 3;

    float w  = __expf(-__expf(decay[c]));
    float eu = __expf(first[c]);
    float num = g_carN[g];
    float den = g_carD[g];

    size_t base = ((size_t)(b * T_ + chunk * L_)) * D_ + c;
    const float* pR  = g_R  + base;
    const float* pEK = g_EK + base;
    const float* pV  = g_V  + base;
    float*       pO  = g_XR + base;                    // reuse as scan output

    float sum = 0.f, sq = 0.f;
#pragma unroll 4
    for (int t = 0; t < L_; t++) {
        float ek = pEK[(size_t)t * D_];
        float v  = pV [(size_t)t * D_];
        float r  = pR [(size_t)t * D_];
        float ee = eu * ek;
        float wkv = __fdividef(num + ee * v, den + ee + EPS_WKV);
        float o = tf32r(r * wkv);
        pO[(size_t)t * D_] = o;
        sum += o;
        sq  += o * o;
        num = num * w + ek * v;
        den = den * w + ek;
    }
#pragma unroll
    for (int off = 16; off; off >>= 1) {
        sum += __shfl_down_sync(0xffffffffu, sum, off);
        sq  += __shfl_down_sync(0xffffffffu, sq,  off);
    }
    if ((threadIdx.x & 31) == 0) {
        int wg = g >> 5;                               // 0..4095
        g_part[wg * 2 + 0] = sum;
        g_part[wg * 2 + 1] = sq;
    }
}

// warp for batch b: indices chunk*256 + b*32 + j
__global__ void stats_kernel()
{
    int b = blockIdx.x;      // 8
    int lane = threadIdx.x;  // 32
    float s = 0.f, q = 0.f;
#pragma unroll
    for (int chunk = 0; chunk < CH_; chunk++) {
        int idx = chunk * 256 + b * 32 + lane;
        s += g_part[idx * 2 + 0];
        q += g_part[idx * 2 + 1];
    }
#pragma unroll
    for (int off = 16; off; off >>= 1) {
        s += __shfl_down_sync(0xffffffffu, s, off);
        q += __shfl_down_sync(0xffffffffu, q, off);
    }
    if (lane == 0) {
        const float N = (float)(T_ * D_);
        float mu = s / N;
        float var = q / N - mu * mu;
        g_stats[2 * b + 0] = mu;
        g_stats[2 * b + 1] = rsqrtf(var + EPS_GN);
    }
}

// -------------------- launch --------------------
extern "C" void kernel_launch(void* const* d_in, const int* in_sizes, int n_in,
                              void* d_out, int out_size)
{
    (void)in_sizes; (void)n_in; (void)out_size;
    const float* x     = (const float*)d_in[0];
    const float* state = (const float*)d_in[1];
    const float* Wr    = (const float*)d_in[2];
    const float* Wk    = (const float*)d_in[3];
    const float* Wv    = (const float*)d_in[4];
    const float* Wo    = (const float*)d_in[5];
    const float* mr    = (const float*)d_in[6];
    const float* mk    = (const float*)d_in[7];
    const float* mv    = (const float*)d_in[8];
    const float* decay = (const float*)d_in[9];
    const float* first = (const float*)d_in[10];
    const float* gam   = (const float*)d_in[11];
    const float* bet   = (const float*)d_in[12];
    float* out = (float*)d_out;

    cudaFuncSetAttribute(gemm_tc<0>, cudaFuncAttributeMaxDynamicSharedMemorySize, SMEM_SZ);
    cudaFuncSetAttribute(gemm_tc<1>, cudaFuncAttributeMaxDynamicSharedMemorySize, SMEM_SZ);
    cudaFuncSetAttribute(gemm_tc<2>, cudaFuncAttributeMaxDynamicSharedMemorySize, SMEM_SZ);
    cudaFuncSetAttribute(gemm_tc<3>, cudaFuncAttributeMaxDynamicSharedMemorySize, SMEM_SZ);

    const int MIX_BLOCKS  = (M_ * D_ / 4) / 256;
    const int RW_BLOCKS   = (D_ * D_ / 4) / 256;
    const int S13_BLOCKS  = (CH_ * B_ * 1024) / 256;
    const int S2_BLOCKS   = (B_ * 1024) / 256;
    const dim3 gg(D_ / 128, M_ / 128);       // (8, 128)

    round_w<<<RW_BLOCKS, 256>>>(Wr, Wk, Wv);
    prep_wo<<<D_, 256>>>(Wo, gam, bet);
    mix_kernel<<<MIX_BLOCKS, 256>>>(x, state, mr, mk, mv);

    gemm_tc<0><<<gg, 256, SMEM_SZ>>>(nullptr);
    gemm_tc<1><<<gg, 256, SMEM_SZ>>>(nullptr);
    gemm_tc<2><<<gg, 256, SMEM_SZ>>>(nullptr);

    scan_part1<<<S13_BLOCKS, 256>>>(decay);
    scan_part2<<<S2_BLOCKS, 256>>>(state, decay);
    scan_part3<<<S13_BLOCKS, 256>>>(decay, first);
    stats_kernel<<<8, 32>>>();

    gemm_tc<3><<<gg, 256, SMEM_SZ>>>(out);
}

// round 9
// speedup vs baseline: 6.5373x; 1.0289x over previous
#include <cuda_runtime.h>
#include <cstdint>

// Problem constants
#define B_ 8
#define T_ 2048
#define D_ 1024
#define M_ (B_ * T_)          // 16384
#define EPS_WKV 1e-9f
#define EPS_GN  1e-5f
#define CH_ 16                 // scan chunks
#define L_ (T_ / CH_)          // 128 steps per chunk

// k-permutation within each 8-group: pos p holds k = [0,4,1,5,2,6,3,7][p]
// perm(k) = (k&~7) | (2*(k&3) + ((k>>2)&1))

// -------------------- device scratch (no allocations allowed) --------------------
__device__ float g_XR[(size_t)M_ * D_];   // xr mix (perm cols); later scan output (perm cols)
__device__ float g_XK[(size_t)M_ * D_];   // perm cols
__device__ float g_XV[(size_t)M_ * D_];   // perm cols
__device__ float g_R [(size_t)M_ * D_];   // natural cols (GEMM outputs)
__device__ float g_EK[(size_t)M_ * D_];
__device__ float g_V [(size_t)M_ * D_];
__device__ float g_Wr[(size_t)D_ * D_];   // tf32-rounded, perm cols
__device__ float g_Wk[(size_t)D_ * D_];
__device__ float g_Wv[(size_t)D_ * D_];
__device__ float g_Wg[(size_t)D_ * D_];   // tf32(gamma ⊙ W_o), perm cols
__device__ float g_c1[D_];
__device__ float g_c2[D_];
__device__ float g_locN[CH_ * B_ * 1024];
__device__ float g_locD[CH_ * B_ * 1024];
__device__ float g_carN[CH_ * B_ * 1024];
__device__ float g_carD[CH_ * B_ * 1024];
__device__ float g_part[8192];
__device__ float g_stats[16];

// -------------------- helpers --------------------
__device__ __forceinline__ float tf32r(float f) {
    uint32_t u;
    asm("cvt.rna.tf32.f32 %0, %1;" : "=r"(u) : "f"(f));
    return __uint_as_float(u);
}
__device__ __forceinline__ void cp16(uint32_t dst, const void* src) {
    asm volatile("cp.async.cg.shared.global [%0], [%1], 16;" :: "r"(dst), "l"(src) : "memory");
}
__device__ __forceinline__ uint32_t smem_u32(const void* p) {
    uint32_t a;
    asm("{ .reg .u64 t; cvta.to.shared.u64 t, %1; cvt.u32.u64 %0, t; }" : "=r"(a) : "l"(p));
    return a;
}
__device__ __forceinline__ void mma_tf32(float* c, const uint32_t* a, const uint32_t* b) {
    asm volatile(
        "mma.sync.aligned.m16n8k8.row.col.f32.tf32.tf32.f32 "
        "{%0,%1,%2,%3}, {%4,%5,%6,%7}, {%8,%9}, {%0,%1,%2,%3};"
        : "+f"(c[0]), "+f"(c[1]), "+f"(c[2]), "+f"(c[3])
        : "r"(a[0]), "r"(a[1]), "r"(a[2]), "r"(a[3]), "r"(b[0]), "r"(b[1]));
}

// -------------------- 1) token-shift + time-mix; outputs tf32-rounded, k-permuted --------------------
// 8 channels per thread; store order [o0,o4,o1,o5] [o2,o6,o3,o7]
__global__ void mix_kernel(const float* __restrict__ x, const float* __restrict__ state,
                           const float* __restrict__ mr, const float* __restrict__ mk,
                           const float* __restrict__ mv)
{
    int i8 = blockIdx.x * blockDim.x + threadIdx.x;
    int elem = i8 * 8;
    int d = elem & (D_ - 1);
    int t = (elem >> 10) & (T_ - 1);

    float4 x0 = *(const float4*)(x + elem);
    float4 x1 = *(const float4*)(x + elem + 4);
    float4 p0, p1;
    if (t == 0) {
        int b = elem >> 21;
        int s0 = ((b << 10) + d) * 3 + 2;
        p0.x = state[s0 + 0];  p0.y = state[s0 + 3];
        p0.z = state[s0 + 6];  p0.w = state[s0 + 9];
        p1.x = state[s0 + 12]; p1.y = state[s0 + 15];
        p1.z = state[s0 + 18]; p1.w = state[s0 + 21];
    } else {
        p0 = *(const float4*)(x + elem - D_);
        p1 = *(const float4*)(x + elem - D_ + 4);
    }

#define MIX8(WPTR, DST)                                                          \
    {                                                                            \
        float4 w0 = *(const float4*)(WPTR + d);                                  \
        float4 w1 = *(const float4*)(WPTR + d + 4);                              \
        float o0 = tf32r(x0.x * w0.x + p0.x * (1.f - w0.x));                     \
        float o1 = tf32r(x0.y * w0.y + p0.y * (1.f - w0.y));                     \
        float o2 = tf32r(x0.z * w0.z + p0.z * (1.f - w0.z));                     \
        float o3 = tf32r(x0.w * w0.w + p0.w * (1.f - w0.w));                     \
        float o4 = tf32r(x1.x * w1.x + p1.x * (1.f - w1.x));                     \
        float o5 = tf32r(x1.y * w1.y + p1.y * (1.f - w1.y));                     \
        float o6 = tf32r(x1.z * w1.z + p1.z * (1.f - w1.z));                     \
        float o7 = tf32r(x1.w * w1.w + p1.w * (1.f - w1.w));                     \
        float4 s0v; s0v.x = o0; s0v.y = o4; s0v.z = o1; s0v.w = o5;              \
        float4 s1v; s1v.x = o2; s1v.y = o6; s1v.z = o3; s1v.w = o7;              \
        *(float4*)(DST + elem) = s0v;                                            \
        *(float4*)(DST + elem + 4) = s1v;                                        \
    }
    MIX8(mr, g_XR)
    MIX8(mk, g_XK)
    MIX8(mv, g_XV)
#undef MIX8
}

// -------------------- 1b) tf32-rounded, k-permuted weight copies --------------------
__global__ void round_w(const float* __restrict__ Wr, const float* __restrict__ Wk,
                        const float* __restrict__ Wv)
{
    int e = (blockIdx.x * blockDim.x + threadIdx.x) * 8;
#define RW8(SRC, DST)                                                            \
    {                                                                            \
        float4 a0 = *(const float4*)(SRC + e);                                   \
        float4 a1 = *(const float4*)(SRC + e + 4);                               \
        float4 s0v; float4 s1v;                                                  \
        s0v.x = tf32r(a0.x); s0v.y = tf32r(a1.x);                                \
        s0v.z = tf32r(a0.y); s0v.w = tf32r(a1.y);                                \
        s1v.x = tf32r(a0.z); s1v.y = tf32r(a1.z);                                \
        s1v.z = tf32r(a0.w); s1v.w = tf32r(a1.w);                                \
        *(float4*)(DST + e) = s0v;                                               \
        *(float4*)(DST + e + 4) = s1v;                                           \
    }
    RW8(Wr, g_Wr)
    RW8(Wk, g_Wk)
    RW8(Wv, g_Wv)
#undef RW8
}

// -------------------- 1c) fold GroupNorm affine into W_o (k-permuted store) --------------------
__global__ void prep_wo(const float* __restrict__ Wo, const float* __restrict__ gam,
                        const float* __restrict__ bet)
{
    __shared__ float sh1[8], sh2[8];
    int n = blockIdx.x;
    float s1 = 0.f, s2 = 0.f;
    for (int k = threadIdx.x; k < D_; k += 256) {
        float w = Wo[n * D_ + k];
        float wg = tf32r(gam[k] * w);
        int kp = (k & ~7) | (2 * (k & 3) + ((k >> 2) & 1));
        g_Wg[(size_t)n * D_ + kp] = wg;
        s1 += wg;
        s2 += bet[k] * w;
    }
#pragma unroll
    for (int off = 16; off; off >>= 1) {
        s1 += __shfl_down_sync(0xffffffffu, s1, off);
        s2 += __shfl_down_sync(0xffffffffu, s2, off);
    }
    if ((threadIdx.x & 31) == 0) { sh1[threadIdx.x >> 5] = s1; sh2[threadIdx.x >> 5] = s2; }
    __syncthreads();
    if (threadIdx.x == 0) {
        float a = 0.f, b = 0.f;
        for (int i = 0; i < 8; i++) { a += sh1[i]; b += sh2[i]; }  // fixed order
        g_c1[n] = a; g_c2[n] = b;
    }
}

// -------------------- 2) tf32 mma.sync GEMM core (LDS.64 fragments, XOR swizzle) ------------
constexpr int BKt = 32;
constexpr int NIT = D_ / BKt;                  // 32
constexpr int TILE_FLOATS = 128 * 32;          // 4096 floats = 16KB
constexpr int STAGE_FLOATS = 2 * TILE_FLOATS;
constexpr int STAGE_BYTES = STAGE_FLOATS * 4;  // 32768
constexpr int STAGES = 3;
constexpr int SMEM_SZ = STAGES * STAGE_BYTES;  // 98304

__device__ __forceinline__ void gemm_body(const float* __restrict__ A, const float* __restrict__ W,
                                          float* smf, uint32_t sb, int m0, int n0,
                                          float c[2][8][4])
{
    const int tid = threadIdx.x;
    const int lane = tid & 31;
    const int wid = tid >> 5;
    const int lr = lane >> 2, lc = lane & 3;
    const int wm = wid & 3, wn = wid >> 2;

#pragma unroll
    for (int mi = 0; mi < 2; mi++)
#pragma unroll
        for (int ni = 0; ni < 8; ni++)
#pragma unroll
            for (int q = 0; q < 4; q++) c[mi][ni][q] = 0.f;

    auto load_stage = [&](int it, int s) {
        int kt = it * BKt;
        uint32_t ab = sb + s * STAGE_BYTES;
        uint32_t bb = ab + TILE_FLOATS * 4;
#pragma unroll
        for (int i = 0; i < 4; i++) {
            int g = tid + i * 256;
            int row = g >> 3;
            int c4 = g & 7;
            uint32_t off = row * 128 + ((c4 * 16) ^ ((row & 3) << 5));
            cp16(ab + off, A + (size_t)(m0 + row) * D_ + kt + c4 * 4);
            cp16(bb + off, W + (size_t)(n0 + row) * D_ + kt + c4 * 4);
        }
        asm volatile("cp.async.commit_group;" ::: "memory");
    };

    load_stage(0, 0);
    load_stage(1, 1);
    asm volatile("cp.async.wait_group 1;" ::: "memory");
    __syncthreads();

    const int sw = (lr & 3) << 3;   // word-XOR for fragment loads (row&3 == lr&3)

    for (int kt = 0; kt < NIT; kt++) {
        int s = kt % STAGES;
        if (kt + 2 < NIT) load_stage(kt + 2, (kt + 2) % STAGES);

        const float* As = smf + s * STAGE_FLOATS;
        const float* Bs = As + TILE_FLOATS;
#pragma unroll
        for (int k0 = 0; k0 < BKt; k0 += 8) {
            const int q = (k0 + 2 * lc) ^ sw;
            uint32_t a[2][4], bf[8][2];
#pragma unroll
            for (int mi = 0; mi < 2; mi++) {
                int row = wm * 32 + mi * 16 + lr;
                float2 av0 = *(const float2*)(As + row * 32 + q);
                float2 av1 = *(const float2*)(As + (row + 8) * 32 + q);
                a[mi][0] = __float_as_uint(av0.x);
                a[mi][2] = __float_as_uint(av0.y);
                a[mi][1] = __float_as_uint(av1.x);
                a[mi][3] = __float_as_uint(av1.y);
            }
#pragma unroll
            for (int ni = 0; ni < 8; ni++) {
                int row = wn * 64 + ni * 8 + lr;
                float2 bv = *(const float2*)(Bs + row * 32 + q);
                bf[ni][0] = __float_as_uint(bv.x);
                bf[ni][1] = __float_as_uint(bv.y);
            }
#pragma unroll
            for (int mi = 0; mi < 2; mi++)
#pragma unroll
                for (int ni = 0; ni < 8; ni++)
                    mma_tf32(c[mi][ni], a[mi], bf[ni]);
        }

        if (kt < NIT - 1) {
            if (kt + 2 < NIT) asm volatile("cp.async.wait_group 1;" ::: "memory");
            else              asm volatile("cp.async.wait_group 0;" ::: "memory");
            __syncthreads();
        }
    }
}

// Fused r/k/v GEMMs: blockIdx.z selects mode 0(sigmoid->g_R) 1(exp->g_EK) 2(->g_V)
__global__ void __launch_bounds__(256, 2)
gemm_qkv()
{
    extern __shared__ float smf[];
    uint32_t sb = smem_u32(smf);
    const int mode = blockIdx.z;
    const int m0 = blockIdx.y * 128;
    const int n0 = blockIdx.x * 128;
    const float* A = (mode == 0) ? g_XR : (mode == 1) ? g_XK : g_XV;
    const float* W = (mode == 0) ? g_Wr : (mode == 1) ? g_Wk : g_Wv;
    float* C = (mode == 0) ? g_R : (mode == 1) ? g_EK : g_V;

    float c[2][8][4];
    gemm_body(A, W, smf, sb, m0, n0, c);

    const int lane = threadIdx.x & 31;
    const int wid = threadIdx.x >> 5;
    const int lr = lane >> 2, lc = lane & 3;
    const int wm = wid & 3, wn = wid >> 2;
#pragma unroll
    for (int mi = 0; mi < 2; mi++) {
#pragma unroll
        for (int half = 0; half < 2; half++) {
            int m = m0 + wm * 32 + mi * 16 + lr + half * 8;
            float* crow = C + (size_t)m * D_ + n0 + wn * 64 + lc * 2;
#pragma unroll
            for (int ni = 0; ni < 8; ni++) {
                float v0 = c[mi][ni][half * 2 + 0];
                float v1 = c[mi][ni][half * 2 + 1];
                float2 o;
                if (mode == 0) {
                    o.x = 1.f / (1.f + __expf(-v0));
                    o.y = 1.f / (1.f + __expf(-v1));
                } else if (mode == 1) {
                    o.x = __expf(v0); o.y = __expf(v1);
                } else {
                    o.x = v0; o.y = v1;
                }
                *(float2*)(crow + ni * 8) = o;
            }
        }
    }
}

// Final GEMM: out = (scan_out normalized) @ (gamma⊙Wo)^T, GN folded algebraically
__global__ void __launch_bounds__(256, 2)
gemm_o(float* __restrict__ Cout)
{
    extern __shared__ float smf[];
    uint32_t sb = smem_u32(smf);
    const int m0 = blockIdx.y * 128;
    const int n0 = blockIdx.x * 128;

    float c[2][8][4];
    gemm_body(g_XR, g_Wg, smf, sb, m0, n0, c);

    const int lane = threadIdx.x & 31;
    const int wid = threadIdx.x >> 5;
    const int lr = lane >> 2, lc = lane & 3;
    const int wm = wid & 3, wn = wid >> 2;

    int b = m0 / T_;
    float mu = g_stats[2 * b];
    float rstd = g_stats[2 * b + 1];
#pragma unroll
    for (int mi = 0; mi < 2; mi++) {
#pragma unroll
        for (int half = 0; half < 2; half++) {
            int m = m0 + wm * 32 + mi * 16 + lr + half * 8;
            float* crow = Cout + (size_t)m * D_ + n0 + wn * 64 + lc * 2;
#pragma unroll
            for (int ni = 0; ni < 8; ni++) {
                float v0 = c[mi][ni][half * 2 + 0];
                float v1 = c[mi][ni][half * 2 + 1];
                int n = n0 + wn * 64 + ni * 8 + lc * 2;
                float2 o;
                o.x = v0 * rstd + (g_c2[n + 0] - mu * rstd * g_c1[n + 0]);
                o.y = v1 * rstd + (g_c2[n + 1] - mu * rstd * g_c1[n + 1]);
                *(float2*)(crow + ni * 8) = o;
            }
        }
    }
}

// -------------------- 3) chunk-parallel WKV scan --------------------
__global__ void scan_part1(const float* __restrict__ decay)
{
    int g = blockIdx.x * blockDim.x + threadIdx.x;
    int c = g & 1023;
    int cb = g >> 10;
    int b = cb & 7;
    int chunk = cb >> 3;

    float w = __expf(-__expf(decay[c]));
    const float* pEK = g_EK + ((size_t)(b * T_ + chunk * L_)) * D_ + c;
    const float* pV  = g_V  + ((size_t)(b * T_ + chunk * L_)) * D_ + c;

    float num = 0.f, den = 0.f;
#pragma unroll 4
    for (int t = 0; t < L_; t++) {
        float ek = pEK[(size_t)t * D_];
        float v  = pV [(size_t)t * D_];
        num = num * w + ek * v;
        den = den * w + ek;
    }
    g_locN[g] = num;
    g_locD[g] = den;
}

__global__ void scan_part2(const float* __restrict__ state, const float* __restrict__ decay)
{
    int g = blockIdx.x * blockDim.x + threadIdx.x;     // 0..8191
    int c = g & 1023;
    int b = g >> 10;
    float wL = __expf(-__expf(decay[c]) * (float)L_);
    float cn = state[((b << 10) + c) * 3 + 0];
    float cd = state[((b << 10) + c) * 3 + 1];
#pragma unroll
    for (int chunk = 0; chunk < CH_; chunk++) {
        int idx = ((chunk << 3) + b) * 1024 + c;
        g_carN[idx] = cn;
        g_carD[idx] = cd;
        cn = cn * wL + g_locN[idx];
        cd = cd * wL + g_locD[idx];
    }
}

__global__ void scan_part3(const float* __restrict__ decay, const float* __restrict__ first)
{
    int g = blockIdx.x * blockDim.x + threadIdx.x;
    int c = g & 1023;
    int cb = g >> 10;
    int b = cb & 7;
    int chunk = cb >> 3;

    float w  = __expf(-__expf(decay[c]));
    float eu = __expf(first[c]);
    float num = g_carN[g];
    float den = g_carD[g];

    size_t base = ((size_t)(b * T_ + chunk * L_)) * D_;
    const float* pR  = g_R  + base + c;
    const float* pEK = g_EK + base + c;
    const float* pV  = g_V  + base + c;
    int cp = (c & ~7) | (2 * (c & 3) + ((c >> 2) & 1));   // permuted column for GEMM-4 input
    float*       pO  = g_XR + base + cp;

    float sum = 0.f, sq = 0.f;
#pragma unroll 4
    for (int t = 0; t < L_; t++) {
        float ek = pEK[(size_t)t * D_];
        float v  = pV [(size_t)t * D_];
        float r  = pR [(size_t)t * D_];
        float ee = eu * ek;
        float wkv = __fdividef(num + ee * v, den + ee + EPS_WKV);
        float o = tf32r(r * wkv);
        pO[(size_t)t * D_] = o;
        sum += o;
        sq  += o * o;
        num = num * w + ek * v;
        den = den * w + ek;
    }
#pragma unroll
    for (int off = 16; off; off >>= 1) {
        sum += __shfl_down_sync(0xffffffffu, sum, off);
        sq  += __shfl_down_sync(0xffffffffu, sq,  off);
    }
    if ((threadIdx.x & 31) == 0) {
        int wg = g >> 5;
        g_part[wg * 2 + 0] = sum;
        g_part[wg * 2 + 1] = sq;
    }
}

__global__ void stats_kernel()
{
    int b = blockIdx.x;
    int lane = threadIdx.x;
    float s = 0.f, q = 0.f;
#pragma unroll
    for (int chunk = 0; chunk < CH_; chunk++) {
        int idx = chunk * 256 + b * 32 + lane;
        s += g_part[idx * 2 + 0];
        q += g_part[idx * 2 + 1];
    }
#pragma unroll
    for (int off = 16; off; off >>= 1) {
        s += __shfl_down_sync(0xffffffffu, s, off);
        q += __shfl_down_sync(0xffffffffu, q, off);
    }
    if (lane == 0) {
        const float N = (float)(T_ * D_);
        float mu = s / N;
        float var = q / N - mu * mu;
        g_stats[2 * b + 0] = mu;
        g_stats[2 * b + 1] = rsqrtf(var + EPS_GN);
    }
}

// -------------------- launch --------------------
extern "C" void kernel_launch(void* const* d_in, const int* in_sizes, int n_in,
                              void* d_out, int out_size)
{
    (void)in_sizes; (void)n_in; (void)out_size;
    const float* x     = (const float*)d_in[0];
    const float* state = (const float*)d_in[1];
    const float* Wr    = (const float*)d_in[2];
    const float* Wk    = (const float*)d_in[3];
    const float* Wv    = (const float*)d_in[4];
    const float* Wo    = (const float*)d_in[5];
    const float* mr    = (const float*)d_in[6];
    const float* mk    = (const float*)d_in[7];
    const float* mv    = (const float*)d_in[8];
    const float* decay = (const float*)d_in[9];
    const float* first = (const float*)d_in[10];
    const float* gam   = (const float*)d_in[11];
    const float* bet   = (const float*)d_in[12];
    float* out = (float*)d_out;

    cudaFuncSetAttribute(gemm_qkv, cudaFuncAttributeMaxDynamicSharedMemorySize, SMEM_SZ);
    cudaFuncSetAttribute(gemm_o,   cudaFuncAttributeMaxDynamicSharedMemorySize, SMEM_SZ);

    const int MIX_BLOCKS = (M_ * D_ / 8) / 256;
    const int RW_BLOCKS  = (D_ * D_ / 8) / 256;
    const int S13_BLOCKS = (CH_ * B_ * 1024) / 256;
    const int S2_BLOCKS  = (B_ * 1024) / 256;

    round_w<<<RW_BLOCKS, 256>>>(Wr, Wk, Wv);
    prep_wo<<<D_, 256>>>(Wo, gam, bet);
    mix_kernel<<<MIX_BLOCKS, 256>>>(x, state, mr, mk, mv);

    dim3 gq(D_ / 128, M_ / 128, 3);          // fused r/k/v GEMMs
    gemm_qkv<<<gq, 256, SMEM_SZ>>>();

    scan_part1<<<S13_BLOCKS, 256>>>(decay);
    scan_part2<<<S2_BLOCKS, 256>>>(state, decay);
    scan_part3<<<S13_BLOCKS, 256>>>(decay, first);
    stats_kernel<<<8, 32>>>();

    dim3 gg(D_ / 128, M_ / 128);
    gemm_o<<<gg, 256, SMEM_SZ>>>(out);
}